// round 2
// baseline (speedup 1.0000x reference)
#include <cuda_runtime.h>
#include <cstdint>

#define N_IN    16
#define N_MF    2
#define N_RULES 64
#define NPAIR   32        // rule pairs
#define TPB     64
#define RPT     2         // rows per thread (packed into f32x2 lanes)

typedef unsigned long long ull;

// ---------- f32x2 helpers (sm_100a packed fp32) ----------
__device__ __forceinline__ ull pack2(float lo, float hi) {
    ull r;
    asm("mov.b64 %0, {%1, %2};" : "=l"(r) : "f"(lo), "f"(hi));
    return r;
}
__device__ __forceinline__ void unpack2(ull v, float& lo, float& hi) {
    asm("mov.b64 {%0, %1}, %2;" : "=f"(lo), "=f"(hi) : "l"(v));
}
__device__ __forceinline__ ull ffma2(ull a, ull b, ull c) {
    ull d;
    asm("fma.rn.f32x2 %0, %1, %2, %3;" : "=l"(d) : "l"(a), "l"(b), "l"(c));
    return d;
}
__device__ __forceinline__ ull fadd2(ull a, ull b) {
    ull d;
    asm("add.rn.f32x2 %0, %1, %2;" : "=l"(d) : "l"(a), "l"(b));
    return d;
}
__device__ __forceinline__ ull fmul2(ull a, ull b) {
    ull d;
    asm("mul.rn.f32x2 %0, %1, %2;" : "=l"(d) : "l"(a), "l"(b));
    return d;
}
__device__ __forceinline__ float ex2_fast(float x) {
    float y;
    asm("ex2.approx.f32 %0, %1;" : "=f"(y) : "f"(x));
    return y;
}

// -0.5 * log2(e), 1/ln(2)
#define NEG_HALF_LOG2E (-0.7213475204444817f)
#define LOG2E          ( 1.4426950408889634f)

__global__ __launch_bounds__(TPB)
void anfis_kernel(const float* __restrict__ x,          // [B,16]
                  const float* __restrict__ center,     // [16,2]
                  const float* __restrict__ log_sigma,  // [16,2]
                  const float* __restrict__ consequent, // [64,17]
                  const int*   __restrict__ rule_idx,   // [64,16]
                  const float* __restrict__ amask,      // [64]
                  float* __restrict__ out, int B)
{
    // Constants packed as (v_r0, v_r0, v_r1, v_r1) per rule pair so one
    // LDS.128 broadcast yields both duplicated f32x2 'b' operands.
    __shared__ float4 s_mask[NPAIR][N_IN];      // mask bits (0/1) duplicated
    __shared__ float4 s_cons[NPAIR][N_IN + 1];  // consequent cols; [16]=bias
    __shared__ float4 s_amd[NPAIR];             // active_mask duplicated
    __shared__ float2 s_vfb[N_IN + 1];          // fallback vector, duplicated
    __shared__ float  s_cen[N_IN][N_MF];
    __shared__ float  s_inv[N_IN][N_MF];        // 1/(exp(log_sigma)+1e-6)

    const int tid = threadIdx.x;

    for (int idx = tid; idx < NPAIR * N_IN; idx += TPB) {
        int p = idx >> 4, i = idx & 15;
        float m0 = (float)rule_idx[(2 * p)     * N_IN + i];
        float m1 = (float)rule_idx[(2 * p + 1) * N_IN + i];
        s_mask[p][i] = make_float4(m0, m0, m1, m1);
    }
    for (int idx = tid; idx < NPAIR * (N_IN + 1); idx += TPB) {
        int p = idx / (N_IN + 1), i = idx % (N_IN + 1);
        float c0 = consequent[(2 * p)     * (N_IN + 1) + i];
        float c1 = consequent[(2 * p + 1) * (N_IN + 1) + i];
        s_cons[p][i] = make_float4(c0, c0, c1, c1);
    }
    if (tid < NPAIR) {
        float a0 = amask[2 * tid], a1 = amask[2 * tid + 1];
        s_amd[tid] = make_float4(a0, a0, a1, a1);
    }
    if (tid < N_IN * N_MF) {
        int i = tid >> 1, j = tid & 1;
        s_cen[i][j] = center[i * N_MF + j];
        s_inv[i][j] = 1.0f / (expf(log_sigma[i * N_MF + j]) + 1e-6f);
    }
    if (tid < N_IN + 1) {
        float asum = 0.f;
        for (int r = 0; r < N_RULES; r++) asum += amask[r];
        float inv = 1.0f / fmaxf(asum, 1.0f);
        float v = 0.f;
        for (int r = 0; r < N_RULES; r++)
            v += amask[r] * consequent[r * (N_IN + 1) + tid];
        v *= inv;
        s_vfb[tid] = make_float2(v, v);
    }
    __syncthreads();

    const int rowA = blockIdx.x * (TPB * RPT) + tid;
    if (rowA >= B) return;
    int rowB = rowA + TPB;
    const bool hasB = (rowB < B);
    if (!hasB) rowB = rowA;  // clamp: duplicate compute, skip store

    // ---- load both rows (float4 vectorized, coalesced) ----
    const float4* xva = reinterpret_cast<const float4*>(x + (size_t)rowA * N_IN);
    const float4* xvb = reinterpret_cast<const float4*>(x + (size_t)rowB * N_IN);
    float4 a0 = xva[0], a1 = xva[1], a2 = xva[2], a3 = xva[3];
    float4 b0 = xvb[0], b1 = xvb[1], b2 = xvb[2], b3 = xvb[3];
    float xA[N_IN] = {a0.x, a0.y, a0.z, a0.w, a1.x, a1.y, a1.z, a1.w,
                      a2.x, a2.y, a2.z, a2.w, a3.x, a3.y, a3.z, a3.w};
    float xB[N_IN] = {b0.x, b0.y, b0.z, b0.w, b1.x, b1.y, b1.z, b1.w,
                      b2.x, b2.y, b2.z, b2.w, b3.x, b3.y, b3.z, b3.w};

    // ---- membership in log2 space, packed (rowA, rowB) ----
    float baseA = 0.f, baseB = 0.f;
    ull diff2[N_IN], xp2[N_IN];
    #pragma unroll
    for (int i = 0; i < N_IN; i++) {
        float c0f = s_cen[i][0], c1f = s_cen[i][1];
        float i0 = s_inv[i][0], i1 = s_inv[i][1];
        float dA0 = (xA[i] - c0f) * i0, dA1 = (xA[i] - c1f) * i1;
        float dB0 = (xB[i] - c0f) * i0, dB1 = (xB[i] - c1f) * i1;
        float lA0 = dA0 * dA0 * NEG_HALF_LOG2E;
        float lA1 = dA1 * dA1 * NEG_HALF_LOG2E;
        float lB0 = dB0 * dB0 * NEG_HALF_LOG2E;
        float lB1 = dB1 * dB1 * NEG_HALF_LOG2E;
        baseA += lA0;
        baseB += lB0;
        diff2[i] = pack2(lA1 - lA0, lB1 - lB0);
        xp2[i]   = pack2(xA[i], xB[i]);
    }
    const ull base2 = pack2(baseA, baseB);

    ull fs2  = 0ull;   // (fsA, fsB)
    ull acc2 = 0ull;   // (accA, accB)

    #pragma unroll 2
    for (int p = 0; p < NPAIR; p++) {
        const ulonglong2* mp = reinterpret_cast<const ulonglong2*>(s_mask[p]);
        const ulonglong2* cp = reinterpret_cast<const ulonglong2*>(s_cons[p]);

        // log2(firing) per rule of the pair, rows packed
        ull t0 = base2, t1 = base2;
        #pragma unroll
        for (int i = 0; i < N_IN; i++) {
            ulonglong2 m = mp[i];
            t0 = ffma2(diff2[i], m.x, t0);
            t1 = ffma2(diff2[i], m.y, t1);
        }

        // rule_out per rule of the pair, rows packed
        ulonglong2 cb = cp[N_IN];
        ull ro0 = cb.x, ro1 = cb.y;
        #pragma unroll
        for (int i = 0; i < N_IN; i++) {
            ulonglong2 c = cp[i];
            ro0 = ffma2(xp2[i], c.x, ro0);
            ro1 = ffma2(xp2[i], c.y, ro1);
        }

        float tA0, tB0, tA1, tB1;
        unpack2(t0, tA0, tB0);
        unpack2(t1, tA1, tB1);
        ull f0 = pack2(ex2_fast(tA0), ex2_fast(tB0));
        ull f1 = pack2(ex2_fast(tA1), ex2_fast(tB1));

        ulonglong2 am = *reinterpret_cast<const ulonglong2*>(&s_amd[p]);
        ull g0 = fmul2(f0, am.x);
        ull g1 = fmul2(f1, am.y);

        fs2  = fadd2(fs2, fadd2(g0, g1));
        acc2 = ffma2(g0, ro0, acc2);
        acc2 = ffma2(g1, ro1, acc2);
    }

    // fallback: v_fb . x_aug  (row-independent v_fb, 17 packed FMAs)
    ull fb2 = *reinterpret_cast<const ull*>(&s_vfb[N_IN]);  // bias term
    #pragma unroll
    for (int i = 0; i < N_IN; i++)
        fb2 = ffma2(xp2[i], *reinterpret_cast<const ull*>(&s_vfb[i]), fb2);

    float fsA, fsB, accA, accB, fbA, fbB;
    unpack2(fs2, fsA, fsB);
    unpack2(acc2, accA, accB);
    unpack2(fb2, fbA, fbB);

    float zA = (fsA <= 1e-12f) ? fbA : __fdividef(accA, fsA);
    float zB = (fsB <= 1e-12f) ? fbB : __fdividef(accB, fsB);

    float sA = __fdividef(1.0f, 1.0f + ex2_fast(-zA * LOG2E));
    float sB = __fdividef(1.0f, 1.0f + ex2_fast(-zB * LOG2E));
    sA = fminf(fmaxf(sA, 1e-7f), 1.0f - 1e-7f);
    sB = fminf(fmaxf(sB, 1e-7f), 1.0f - 1e-7f);

    out[rowA] = sA;
    if (hasB) out[rowA + TPB] = sB;
}

extern "C" void kernel_launch(void* const* d_in, const int* in_sizes, int n_in,
                              void* d_out, int out_size)
{
    const float* x          = (const float*)d_in[0];
    const float* center     = (const float*)d_in[1];
    const float* log_sigma  = (const float*)d_in[2];
    const float* consequent = (const float*)d_in[3];
    const int*   rule_idx   = (const int*)  d_in[4];
    const float* amask      = (const float*)d_in[5];
    float*       out        = (float*)d_out;

    int B = in_sizes[0] / N_IN;
    int rows_per_block = TPB * RPT;
    int grid = (B + rows_per_block - 1) / rows_per_block;
    anfis_kernel<<<grid, TPB>>>(x, center, log_sigma, consequent, rule_idx,
                                amask, out, B);
}